// round 2
// baseline (speedup 1.0000x reference)
#include <cuda_runtime.h>
#include <math.h>

#define NB 4
#define NH 16
#define NS 1024
#define ND 64
#define TQ 32
#define TK 256
#define NT 256

#define KST_STRIDE 65   // k tile row stride (odd -> conflict-free interleaved reads)
#define QS_STRIDE  68   // q tile row stride

// Precomputed rescale factor: (1+e)/(1+exp(1-dist)), shared across all 16 heads.
__device__ float g_resc[NB * NS * NS];

__global__ void rescale_kernel(const float* __restrict__ dist) {
    int i = blockIdx.x * blockDim.x + threadIdx.x;
    float d = dist[i];
    g_resc[i] = 3.7182817f / (1.0f + __expf(1.0f - d));
}

__global__ __launch_bounds__(NT, 1)
void attn_kernel(const float* __restrict__ q,
                 const float* __restrict__ k,
                 const float* __restrict__ v,
                 const int*   __restrict__ mask,
                 const float* __restrict__ adj,
                 float*       __restrict__ out,
                 float*       __restrict__ attn_out) {
    extern __shared__ float smem[];
    float* qs   = smem;                          // TQ * QS_STRIDE       (2176 f)
    float* kst  = qs + TQ * QS_STRIDE;           // TK * KST_STRIDE      (16640 f) ; reused as v tile (256*64)
    float* sc   = kst + TK * KST_STRIDE;         // TQ * NS              (32768 f)
    float* rinv = sc + TQ * NS;                  // TQ
    int*   ms   = (int*)(rinv + TQ);             // NS

    const int tid = threadIdx.x;
    const int q0  = blockIdx.x * TQ;
    const int h   = blockIdx.y;
    const int b   = blockIdx.z;
    const size_t bh = (size_t)b * NH + h;

    const float* qg = q + (bh * NS + q0) * ND;
    const float* kg = k + bh * NS * ND;
    const float* vg = v + bh * NS * ND;

    // ---- load q tile (pre-scaled by 1/TEMPERATURE) + mask ----
    for (int i = tid; i < TQ * (ND / 4); i += NT) {
        int r = i >> 4, c = (i & 15) << 2;
        float4 t = *(const float4*)(qg + (size_t)r * ND + c);
        float* dst = qs + r * QS_STRIDE + c;
        dst[0] = t.x * 0.125f; dst[1] = t.y * 0.125f;
        dst[2] = t.z * 0.125f; dst[3] = t.w * 0.125f;
    }
    for (int i = tid; i < NS; i += NT) ms[i] = mask[b * NS + i];

    const int rg = tid >> 5;   // 0..7   (4 q rows each)
    const int cg = tid & 31;   // 0..31  (8 interleaved k cols each)

    // ================= Phase A: scores =================
    for (int kt = 0; kt < NS / TK; kt++) {
        __syncthreads();
        // load k tile, row-major, stride 65
        for (int i = tid; i < TK * (ND / 4); i += NT) {
            int row = i >> 4, c = (i & 15) << 2;
            float4 t = *(const float4*)(kg + (size_t)(kt * TK + row) * ND + c);
            float* dst = kst + row * KST_STRIDE + c;
            dst[0] = t.x; dst[1] = t.y; dst[2] = t.z; dst[3] = t.w;
        }
        __syncthreads();

        float acc[4][8];
        #pragma unroll
        for (int i = 0; i < 4; i++)
            #pragma unroll
            for (int j = 0; j < 8; j++) acc[i][j] = 0.0f;

        const float* qsr = qs + (rg * 4) * QS_STRIDE;
        const float* ksr = kst + cg * KST_STRIDE;   // kc = cg + 32*j

        #pragma unroll 4
        for (int d = 0; d < ND; d++) {
            float kv[8];
            #pragma unroll
            for (int j = 0; j < 8; j++)
                kv[j] = ksr[j * 32 * KST_STRIDE + d];
            #pragma unroll
            for (int i = 0; i < 4; i++) {
                float qv = qsr[i * QS_STRIDE + d];
                #pragma unroll
                for (int j = 0; j < 8; j++)
                    acc[i][j] = fmaf(qv, kv[j], acc[i][j]);
            }
        }

        // epilogue: relu * rescale + adj, mask, store to smem scores
        #pragma unroll
        for (int i = 0; i < 4; i++) {
            int qrow = q0 + rg * 4 + i;
            const float* rp = g_resc + ((size_t)b * NS + qrow) * NS + kt * TK;
            const float* ap = adj    + ((size_t)b * NS + qrow) * NS + kt * TK;
            float* scr = sc + (rg * 4 + i) * NS + kt * TK;
            #pragma unroll
            for (int j = 0; j < 8; j++) {
                int kc = cg + 32 * j;
                float s = fmaxf(acc[i][j], 0.0f) * rp[kc] + ap[kc];
                if (ms[kt * TK + kc] == 0) s = -1.0e9f;
                scr[kc] = s;
            }
        }
    }
    __syncthreads();

    // ================= Phase B: softmax (warp per 4 rows) =================
    {
        int lane = cg;
        for (int i = 0; i < 4; i++) {
            int row = rg * 4 + i;
            float* sr = sc + row * NS;
            float m = -1.0e30f;
            for (int c = lane; c < NS; c += 32) m = fmaxf(m, sr[c]);
            #pragma unroll
            for (int o = 16; o > 0; o >>= 1)
                m = fmaxf(m, __shfl_xor_sync(0xffffffffu, m, o));
            float ssum = 0.0f;
            for (int c = lane; c < NS; c += 32) {
                float p = __expf(sr[c] - m);
                sr[c] = p;
                ssum += p;
            }
            #pragma unroll
            for (int o = 16; o > 0; o >>= 1)
                ssum += __shfl_xor_sync(0xffffffffu, ssum, o);
            if (lane == 0) rinv[row] = 1.0f / ssum;
        }
    }
    __syncthreads();

    // write normalized attn to gmem (coalesced float4)
    {
        float* ag = attn_out + (bh * NS + q0) * NS;
        for (int i = tid; i < TQ * (NS / 4); i += NT) {
            int row = i >> 8, c = (i & 255) << 2;
            float rv = rinv[row];
            float4 p = *(const float4*)(sc + row * NS + c);
            p.x *= rv; p.y *= rv; p.z *= rv; p.w *= rv;
            *(float4*)(ag + (size_t)row * NS + c) = p;
        }
    }

    // ================= Phase C: output = P @ V =================
    const int half = tid >> 7;      // kk split
    const int tt   = tid & 127;
    const int rg2  = tt >> 4;       // 0..7 (4 q rows)
    const int cg2  = tt & 15;       // 0..15 (4 d cols)
    float acc2[4][4];
    #pragma unroll
    for (int i = 0; i < 4; i++)
        #pragma unroll
        for (int j = 0; j < 4; j++) acc2[i][j] = 0.0f;

    for (int vt = 0; vt < NS / TK; vt++) {
        __syncthreads();
        for (int i = tid; i < TK * (ND / 4); i += NT) {
            int row = i >> 4, c = (i & 15) << 2;
            *(float4*)(kst + row * ND + c) =
                *(const float4*)(vg + (size_t)(vt * TK + row) * ND + c);
        }
        __syncthreads();

        const float* scr = sc + (rg2 * 4) * NS + vt * TK + half * 128;
        const float* vsr = kst + half * 128 * ND + cg2 * 4;
        #pragma unroll 2
        for (int kk = 0; kk < 128; kk += 4) {
            float4 vv0 = *(const float4*)(vsr + (kk + 0) * ND);
            float4 vv1 = *(const float4*)(vsr + (kk + 1) * ND);
            float4 vv2 = *(const float4*)(vsr + (kk + 2) * ND);
            float4 vv3 = *(const float4*)(vsr + (kk + 3) * ND);
            #pragma unroll
            for (int i = 0; i < 4; i++) {
                float4 p = *(const float4*)(scr + i * NS + kk);
                acc2[i][0] = fmaf(p.x, vv0.x, acc2[i][0]);
                acc2[i][1] = fmaf(p.x, vv0.y, acc2[i][1]);
                acc2[i][2] = fmaf(p.x, vv0.z, acc2[i][2]);
                acc2[i][3] = fmaf(p.x, vv0.w, acc2[i][3]);
                acc2[i][0] = fmaf(p.y, vv1.x, acc2[i][0]);
                acc2[i][1] = fmaf(p.y, vv1.y, acc2[i][1]);
                acc2[i][2] = fmaf(p.y, vv1.z, acc2[i][2]);
                acc2[i][3] = fmaf(p.y, vv1.w, acc2[i][3]);
                acc2[i][0] = fmaf(p.z, vv2.x, acc2[i][0]);
                acc2[i][1] = fmaf(p.z, vv2.y, acc2[i][1]);
                acc2[i][2] = fmaf(p.z, vv2.z, acc2[i][2]);
                acc2[i][3] = fmaf(p.z, vv2.w, acc2[i][3]);
                acc2[i][0] = fmaf(p.w, vv3.x, acc2[i][0]);
                acc2[i][1] = fmaf(p.w, vv3.y, acc2[i][1]);
                acc2[i][2] = fmaf(p.w, vv3.z, acc2[i][2]);
                acc2[i][3] = fmaf(p.w, vv3.w, acc2[i][3]);
            }
        }
    }
    __syncthreads();

    // reduce the two kk-halves via smem (reuse qs), write output
    if (half == 1) {
        #pragma unroll
        for (int i = 0; i < 4; i++) {
            float* dst = qs + (rg2 * 4 + i) * QS_STRIDE + cg2 * 4;
            *(float4*)dst = make_float4(acc2[i][0], acc2[i][1], acc2[i][2], acc2[i][3]);
        }
    }
    __syncthreads();
    if (half == 0) {
        #pragma unroll
        for (int i = 0; i < 4; i++) {
            int row = rg2 * 4 + i;
            float rv = rinv[row];
            const float* red = qs + row * QS_STRIDE + cg2 * 4;
            float4 o;
            o.x = (acc2[i][0] + red[0]) * rv;
            o.y = (acc2[i][1] + red[1]) * rv;
            o.z = (acc2[i][2] + red[2]) * rv;
            o.w = (acc2[i][3] + red[3]) * rv;
            *(float4*)(out + (bh * NS + (size_t)(q0 + row)) * ND + cg2 * 4) = o;
        }
    }
}

extern "C" void kernel_launch(void* const* d_in, const int* in_sizes, int n_in,
                              void* d_out, int out_size) {
    const float* q    = (const float*)d_in[0];
    const float* k    = (const float*)d_in[1];
    const float* v    = (const float*)d_in[2];
    const int*   mask = (const int*)  d_in[3];
    const float* adj  = (const float*)d_in[4];
    const float* dist = (const float*)d_in[5];

    float* out  = (float*)d_out;                               // [B,H,S,D]
    float* attn = out + (size_t)NB * NH * NS * ND;             // [B,H,S,S]

    // Precompute head-independent rescale factors.
    rescale_kernel<<<(NB * NS * NS) / 256, 256>>>(dist);

    const size_t smem_bytes =
        (size_t)(TQ * QS_STRIDE + TK * KST_STRIDE + TQ * NS + TQ) * sizeof(float)
        + NS * sizeof(int);
    cudaFuncSetAttribute(attn_kernel,
                         cudaFuncAttributeMaxDynamicSharedMemorySize,
                         (int)smem_bytes);

    dim3 grid(NS / TQ, NH, NB);
    attn_kernel<<<grid, NT, smem_bytes>>>(q, k, v, mask, adj, out, attn);
}

// round 3
// speedup vs baseline: 1.3065x; 1.3065x over previous
#include <cuda_runtime.h>
#include <math.h>
#include <stdint.h>

#define NB 4
#define NH 16
#define NS 1024
#define ND 64
#define TQ 32
#define TK 128
#define NT 256

#define QSS 68      // q tile stride   (mod 32 == 4 -> conflict-free (4g+tg))
#define KSS 68      // k tile stride   (mod 32 == 4)
#define VSS 72      // v tile stride   (mod 32 == 8 -> conflict-free (8tg+g))
#define SCS 1028    // scores stride   (mod 32 == 4)

// Precomputed, head-independent tables.
__device__ float g_resc[NB * NS * NS];   // (1+e)/(1+exp(1-dist))
__device__ float g_madj[NB * NS * NS];   // mask ? adj : -1e9

__global__ void prep_kernel(const float* __restrict__ dist,
                            const float* __restrict__ adj,
                            const int*   __restrict__ mask) {
    int i = blockIdx.x * blockDim.x + threadIdx.x;
    int b = i >> 20;            // NS*NS = 1<<20
    int j = i & (NS - 1);       // k-column
    float d = dist[i];
    g_resc[i] = 3.7182817f / (1.0f + __expf(1.0f - d));
    g_madj[i] = (mask[b * NS + j] == 0) ? -1.0e9f : adj[i];
}

__device__ __forceinline__ uint32_t f2tf(float f) {
    uint32_t r;
    asm("cvt.rna.tf32.f32 %0, %1;" : "=r"(r) : "f"(f));
    return r;
}
__device__ __forceinline__ void split_tf32(float f, uint32_t& hi, uint32_t& lo) {
    hi = f2tf(f);
    lo = f2tf(f - __uint_as_float(hi));
}
__device__ __forceinline__ void mma_tf32(float& c0, float& c1, float& c2, float& c3,
                                         uint32_t a0, uint32_t a1, uint32_t a2, uint32_t a3,
                                         uint32_t b0, uint32_t b1) {
    asm volatile("mma.sync.aligned.m16n8k8.row.col.f32.tf32.tf32.f32 "
                 "{%0,%1,%2,%3}, {%4,%5,%6,%7}, {%8,%9}, {%0,%1,%2,%3};"
                 : "+f"(c0), "+f"(c1), "+f"(c2), "+f"(c3)
                 : "r"(a0), "r"(a1), "r"(a2), "r"(a3), "r"(b0), "r"(b1));
}

__global__ __launch_bounds__(NT, 1)
void attn_kernel(const float* __restrict__ q,
                 const float* __restrict__ k,
                 const float* __restrict__ v,
                 float*       __restrict__ out,
                 float*       __restrict__ attn_out) {
    extern __shared__ float smem[];
    float* qs   = smem;                      // TQ * QSS              (2176 f)
    float* kst  = qs + TQ * QSS;             // max(TK*KSS, TK*VSS)   (9216 f)
    float* sc   = kst + TK * VSS;            // TQ * SCS              (32896 f)
    float* rinv = sc + TQ * SCS;             // TQ

    const int tid  = threadIdx.x;
    const int wid  = tid >> 5;
    const int lane = tid & 31;
    const int g    = lane >> 2;   // 0..7
    const int tg   = lane & 3;    // 0..3
    const int wm   = wid >> 2;    // 0..1  (16-row m group)
    const int wn   = wid & 3;     // 0..3  (n group)

    const int q0 = blockIdx.x * TQ;
    const int h  = blockIdx.y;
    const int b  = blockIdx.z;
    const size_t bh = (size_t)b * NH + h;

    const float* qg = q + (bh * NS + q0) * ND;
    const float* kg = k + bh * NS * ND;
    const float* vg = v + bh * NS * ND;

    // ---- load q tile (prescaled by 1/8) ----
    for (int i = tid; i < TQ * (ND / 4); i += NT) {
        int r = i >> 4, c = (i & 15) << 2;
        float4 t = *(const float4*)(qg + (size_t)r * ND + c);
        float* dst = qs + r * QSS + c;
        dst[0] = t.x * 0.125f; dst[1] = t.y * 0.125f;
        dst[2] = t.z * 0.125f; dst[3] = t.w * 0.125f;
    }
    __syncthreads();

    // ---- A fragments (q) : load once, split to hi/lo tf32 ----
    uint32_t ahi[8][4], alo[8][4];
    {
        const int r0 = wm * 16 + g;
        #pragma unroll
        for (int ks = 0; ks < 8; ks++) {
            int col = ks * 8 + tg;
            float f0 = qs[r0 * QSS + col];
            float f1 = qs[(r0 + 8) * QSS + col];
            float f2 = qs[r0 * QSS + col + 4];
            float f3 = qs[(r0 + 8) * QSS + col + 4];
            split_tf32(f0, ahi[ks][0], alo[ks][0]);
            split_tf32(f1, ahi[ks][1], alo[ks][1]);
            split_tf32(f2, ahi[ks][2], alo[ks][2]);
            split_tf32(f3, ahi[ks][3], alo[ks][3]);
        }
    }

    // ================= Phase A: scores = QK^T (3-pass split tf32) ==========
    for (int kt = 0; kt < NS / TK; kt++) {
        __syncthreads();
        for (int i = tid; i < TK * (ND / 4); i += NT) {
            int r = i >> 4, c = (i & 15) << 2;
            float4 t = *(const float4*)(kg + (size_t)(kt * TK + r) * ND + c);
            float* dst = kst + r * KSS + c;
            dst[0] = t.x; dst[1] = t.y; dst[2] = t.z; dst[3] = t.w;
        }
        __syncthreads();

        float c4[4][4];
        #pragma unroll
        for (int nt = 0; nt < 4; nt++)
            #pragma unroll
            for (int j = 0; j < 4; j++) c4[nt][j] = 0.0f;

        #pragma unroll
        for (int ks = 0; ks < 8; ks++) {
            #pragma unroll
            for (int nt = 0; nt < 4; nt++) {
                int nloc = wn * 32 + nt * 8;
                const float* bp = kst + (nloc + g) * KSS + ks * 8 + tg;
                float b0f = bp[0];
                float b1f = bp[4];
                uint32_t b0h, b0l, b1h, b1l;
                split_tf32(b0f, b0h, b0l);
                split_tf32(b1f, b1h, b1l);
                mma_tf32(c4[nt][0], c4[nt][1], c4[nt][2], c4[nt][3],
                         alo[ks][0], alo[ks][1], alo[ks][2], alo[ks][3], b0h, b1h);
                mma_tf32(c4[nt][0], c4[nt][1], c4[nt][2], c4[nt][3],
                         ahi[ks][0], ahi[ks][1], ahi[ks][2], ahi[ks][3], b0l, b1l);
                mma_tf32(c4[nt][0], c4[nt][1], c4[nt][2], c4[nt][3],
                         ahi[ks][0], ahi[ks][1], ahi[ks][2], ahi[ks][3], b0h, b1h);
            }
        }

        // epilogue: relu * rescale + masked_adj -> smem scores
        const int r_lo = wm * 16 + g;
        const int qr_lo = q0 + r_lo;
        #pragma unroll
        for (int nt = 0; nt < 4; nt++) {
            int kc = kt * TK + wn * 32 + nt * 8 + 2 * tg;
            const float2 rl = *(const float2*)(g_resc + ((size_t)b * NS + qr_lo) * NS + kc);
            const float2 al = *(const float2*)(g_madj + ((size_t)b * NS + qr_lo) * NS + kc);
            const float2 rh = *(const float2*)(g_resc + ((size_t)b * NS + qr_lo + 8) * NS + kc);
            const float2 ah = *(const float2*)(g_madj + ((size_t)b * NS + qr_lo + 8) * NS + kc);
            float2 s0, s1;
            s0.x = fmaxf(c4[nt][0], 0.0f) * rl.x + al.x;
            s0.y = fmaxf(c4[nt][1], 0.0f) * rl.y + al.y;
            s1.x = fmaxf(c4[nt][2], 0.0f) * rh.x + ah.x;
            s1.y = fmaxf(c4[nt][3], 0.0f) * rh.y + ah.y;
            *(float2*)(sc + r_lo * SCS + kc) = s0;
            *(float2*)(sc + (r_lo + 8) * SCS + kc) = s1;
        }
    }
    __syncthreads();

    // ================= Phase B: softmax (warp per 4 rows) =================
    {
        #pragma unroll
        for (int i = 0; i < 4; i++) {
            int row = wid * 4 + i;
            float* sr = sc + row * SCS;
            float m = -1.0e30f;
            for (int c = lane; c < NS; c += 32) m = fmaxf(m, sr[c]);
            #pragma unroll
            for (int o = 16; o > 0; o >>= 1)
                m = fmaxf(m, __shfl_xor_sync(0xffffffffu, m, o));
            float ssum = 0.0f;
            for (int c = lane; c < NS; c += 32) {
                float p = __expf(sr[c] - m);
                sr[c] = p;
                ssum += p;
            }
            #pragma unroll
            for (int o = 16; o > 0; o >>= 1)
                ssum += __shfl_xor_sync(0xffffffffu, ssum, o);
            if (lane == 0) rinv[row] = 1.0f / ssum;
        }
    }
    __syncthreads();

    // ---- write normalized attn ----
    {
        float* ag = attn_out + (bh * NS + q0) * NS;
        for (int i = tid; i < TQ * (NS / 4); i += NT) {
            int row = i >> 8, c = (i & 255) << 2;
            float rv = rinv[row];
            float4 p = *(const float4*)(sc + row * SCS + c);
            p.x *= rv; p.y *= rv; p.z *= rv; p.w *= rv;
            *(float4*)(ag + (size_t)row * NS + c) = p;
        }
    }

    // ================= Phase C: out = P @ V (tf32) =================
    float c2[2][4];
    #pragma unroll
    for (int nt = 0; nt < 2; nt++)
        #pragma unroll
        for (int j = 0; j < 4; j++) c2[nt][j] = 0.0f;

    const int m0 = wm * 16;
    for (int vt = 0; vt < NS / TK; vt++) {
        __syncthreads();
        for (int i = tid; i < TK * (ND / 4); i += NT) {
            int r = i >> 4, c = (i & 15) << 2;
            float4 t = *(const float4*)(vg + (size_t)(vt * TK + r) * ND + c);
            float* dst = kst + r * VSS + c;
            dst[0] = t.x; dst[1] = t.y; dst[2] = t.z; dst[3] = t.w;
        }
        __syncthreads();

        #pragma unroll
        for (int ks = 0; ks < 16; ks++) {
            int k0 = vt * TK + ks * 8;
            uint32_t a0 = f2tf(sc[(m0 + g) * SCS + k0 + tg]);
            uint32_t a1 = f2tf(sc[(m0 + g + 8) * SCS + k0 + tg]);
            uint32_t a2 = f2tf(sc[(m0 + g) * SCS + k0 + tg + 4]);
            uint32_t a3 = f2tf(sc[(m0 + g + 8) * SCS + k0 + tg + 4]);
            #pragma unroll
            for (int nt = 0; nt < 2; nt++) {
                int n0 = wn * 16 + nt * 8;
                uint32_t b0 = f2tf(kst[(ks * 8 + tg) * VSS + n0 + g]);
                uint32_t b1 = f2tf(kst[(ks * 8 + tg + 4) * VSS + n0 + g]);
                mma_tf32(c2[nt][0], c2[nt][1], c2[nt][2], c2[nt][3],
                         a0, a1, a2, a3, b0, b1);
            }
        }
    }

    // ---- epilogue: normalize + write out ----
    {
        const int r_lo = m0 + g;
        float rv_lo = rinv[r_lo];
        float rv_hi = rinv[r_lo + 8];
        #pragma unroll
        for (int nt = 0; nt < 2; nt++) {
            int col = wn * 16 + nt * 8 + 2 * tg;
            float2 o0, o1;
            o0.x = c2[nt][0] * rv_lo; o0.y = c2[nt][1] * rv_lo;
            o1.x = c2[nt][2] * rv_hi; o1.y = c2[nt][3] * rv_hi;
            *(float2*)(out + (bh * NS + (size_t)(q0 + r_lo)) * ND + col) = o0;
            *(float2*)(out + (bh * NS + (size_t)(q0 + r_lo + 8)) * ND + col) = o1;
        }
    }
}

extern "C" void kernel_launch(void* const* d_in, const int* in_sizes, int n_in,
                              void* d_out, int out_size) {
    const float* q    = (const float*)d_in[0];
    const float* k    = (const float*)d_in[1];
    const float* v    = (const float*)d_in[2];
    const int*   mask = (const int*)  d_in[3];
    const float* adj  = (const float*)d_in[4];
    const float* dist = (const float*)d_in[5];

    float* out  = (float*)d_out;                      // [B,H,S,D]
    float* attn = out + (size_t)NB * NH * NS * ND;    // [B,H,S,S]

    prep_kernel<<<(NB * NS * NS) / 256, 256>>>(dist, adj, mask);

    const size_t smem_bytes =
        (size_t)(TQ * QSS + TK * VSS + TQ * SCS + TQ) * sizeof(float);
    cudaFuncSetAttribute(attn_kernel,
                         cudaFuncAttributeMaxDynamicSharedMemorySize,
                         (int)smem_bytes);

    dim3 grid(NS / TQ, NH, NB);
    attn_kernel<<<grid, NT, smem_bytes>>>(q, k, v, out, attn);
}

// round 4
// speedup vs baseline: 1.7522x; 1.3411x over previous
#include <cuda_runtime.h>
#include <math.h>
#include <stdint.h>

#define NB 4
#define NH 16
#define NS 1024
#define ND 64
#define TQ 32
#define TK 128
#define NT 512

#define QSS 68      // q hi/lo tile stride (mod 32 == 4 -> conflict-free (4g+tg))
#define KSS 68      // k tile stride       (mod 32 == 4)
#define VSS 72      // v tile stride       (mod 32 == 8 -> conflict-free (8tg+g))
#define SCS 1028    // scores stride       (mod 32 == 4)

// Precomputed, head-independent tables.
__device__ float g_resc[NB * NS * NS];   // (1+e)/(1+exp(1-dist))
__device__ float g_madj[NB * NS * NS];   // mask ? adj : -1e9

__global__ void prep_kernel(const float* __restrict__ dist,
                            const float* __restrict__ adj,
                            const int*   __restrict__ mask) {
    int i = blockIdx.x * blockDim.x + threadIdx.x;
    int b = i >> 20;
    int j = i & (NS - 1);
    float d = dist[i];
    g_resc[i] = 3.7182817f / (1.0f + __expf(1.0f - d));
    g_madj[i] = (mask[b * NS + j] == 0) ? -1.0e9f : adj[i];
}

__device__ __forceinline__ uint32_t f2tf(float f) {
    uint32_t r;
    asm("cvt.rna.tf32.f32 %0, %1;" : "=r"(r) : "f"(f));
    return r;
}
__device__ __forceinline__ void split_tf32(float f, uint32_t& hi, uint32_t& lo) {
    hi = f2tf(f);
    lo = f2tf(f - __uint_as_float(hi));
}
__device__ __forceinline__ void mma_tf32(float& c0, float& c1, float& c2, float& c3,
                                         uint32_t a0, uint32_t a1, uint32_t a2, uint32_t a3,
                                         uint32_t b0, uint32_t b1) {
    asm volatile("mma.sync.aligned.m16n8k8.row.col.f32.tf32.tf32.f32 "
                 "{%0,%1,%2,%3}, {%4,%5,%6,%7}, {%8,%9}, {%0,%1,%2,%3};"
                 : "+f"(c0), "+f"(c1), "+f"(c2), "+f"(c3)
                 : "r"(a0), "r"(a1), "r"(a2), "r"(a3), "r"(b0), "r"(b1));
}

__device__ __forceinline__ void cp_async16(float* smem_dst, const float* gsrc) {
    uint32_t sa = (uint32_t)__cvta_generic_to_shared(smem_dst);
    asm volatile("cp.async.cg.shared.global [%0], [%1], 16;" :: "r"(sa), "l"(gsrc));
}
#define CP_COMMIT()  asm volatile("cp.async.commit_group;")
#define CP_WAIT(n)   asm volatile("cp.async.wait_group %0;" :: "n"(n))

__global__ __launch_bounds__(NT, 1)
void attn_kernel(const float* __restrict__ q,
                 const float* __restrict__ k,
                 const float* __restrict__ v,
                 float*       __restrict__ out,
                 float*       __restrict__ attn_out) {
    extern __shared__ float smem[];
    float* qhi  = smem;                      // TQ*QSS
    float* qlo  = qhi + TQ * QSS;            // TQ*QSS
    float* kbuf = qlo + TQ * QSS;            // 2 * TK * VSS (k uses KSS, v uses VSS)
    float* sc   = kbuf + 2 * TK * VSS;       // TQ * SCS
    float* rinv = sc + TQ * SCS;             // TQ

    const int tid  = threadIdx.x;
    const int wid  = tid >> 5;
    const int lane = tid & 31;
    const int g    = lane >> 2;   // 0..7
    const int tg   = lane & 3;    // 0..3
    const int wm   = wid >> 3;    // 0..1
    const int wn   = wid & 7;     // 0..7

    const int q0 = blockIdx.x * TQ;
    const int h  = blockIdx.y;
    const int b  = blockIdx.z;
    const size_t bh = (size_t)b * NH + h;

    const float* qg = q + (bh * NS + q0) * ND;
    const float* kg = k + bh * NS * ND;
    const float* vg = v + bh * NS * ND;

    // ---- prefetch k tiles 0,1 ----
    for (int t = 0; t < 2; t++) {
        float* dst = kbuf + t * TK * VSS;
        for (int i = tid; i < TK * 16; i += NT) {
            int r = i >> 4, c = (i & 15) << 2;
            cp_async16(dst + r * KSS + c, kg + (size_t)(t * TK + r) * ND + c);
        }
        CP_COMMIT();
    }

    // ---- load q tile, prescale by 1/8, split to hi/lo ----
    {
        int i = tid;   // TQ*16 = 512 float4 chunks, exactly one per thread
        int r = i >> 4, c = (i & 15) << 2;
        float4 t = *(const float4*)(qg + (size_t)r * ND + c);
        uint32_t h0, l0, h1, l1, h2, l2, h3, l3;
        split_tf32(t.x * 0.125f, h0, l0);
        split_tf32(t.y * 0.125f, h1, l1);
        split_tf32(t.z * 0.125f, h2, l2);
        split_tf32(t.w * 0.125f, h3, l3);
        float* dh = qhi + r * QSS + c;
        float* dl = qlo + r * QSS + c;
        dh[0] = __uint_as_float(h0); dh[1] = __uint_as_float(h1);
        dh[2] = __uint_as_float(h2); dh[3] = __uint_as_float(h3);
        dl[0] = __uint_as_float(l0); dl[1] = __uint_as_float(l1);
        dl[2] = __uint_as_float(l2); dl[3] = __uint_as_float(l3);
    }

    const int m0 = wm * 16;
    const int r_lo = m0 + g;

    // ================= Phase A: scores = QK^T (3-pass split tf32) ==========
    for (int kt = 0; kt < NS / TK; kt++) {
        if (kt < 7) { CP_WAIT(1); } else { CP_WAIT(0); }
        __syncthreads();

        const float* kb = kbuf + (kt & 1) * TK * VSS;

        float c4[2][4];
        #pragma unroll
        for (int nt = 0; nt < 2; nt++)
            #pragma unroll
            for (int j = 0; j < 4; j++) c4[nt][j] = 0.0f;

        #pragma unroll
        for (int ks = 0; ks < 8; ks++) {
            int col = ks * 8 + tg;
            uint32_t ah0 = __float_as_uint(qhi[r_lo * QSS + col]);
            uint32_t ah1 = __float_as_uint(qhi[(r_lo + 8) * QSS + col]);
            uint32_t ah2 = __float_as_uint(qhi[r_lo * QSS + col + 4]);
            uint32_t ah3 = __float_as_uint(qhi[(r_lo + 8) * QSS + col + 4]);
            uint32_t al0 = __float_as_uint(qlo[r_lo * QSS + col]);
            uint32_t al1 = __float_as_uint(qlo[(r_lo + 8) * QSS + col]);
            uint32_t al2 = __float_as_uint(qlo[r_lo * QSS + col + 4]);
            uint32_t al3 = __float_as_uint(qlo[(r_lo + 8) * QSS + col + 4]);
            #pragma unroll
            for (int nt = 0; nt < 2; nt++) {
                int nloc = wn * 16 + nt * 8;
                const float* bp = kb + (nloc + g) * KSS + col;
                float b0f = bp[0];
                float b1f = bp[4];
                uint32_t b0h, b0l, b1h, b1l;
                split_tf32(b0f, b0h, b0l);
                split_tf32(b1f, b1h, b1l);
                mma_tf32(c4[nt][0], c4[nt][1], c4[nt][2], c4[nt][3],
                         al0, al1, al2, al3, b0h, b1h);
                mma_tf32(c4[nt][0], c4[nt][1], c4[nt][2], c4[nt][3],
                         ah0, ah1, ah2, ah3, b0l, b1l);
                mma_tf32(c4[nt][0], c4[nt][1], c4[nt][2], c4[nt][3],
                         ah0, ah1, ah2, ah3, b0h, b1h);
            }
        }

        // epilogue: relu * rescale + masked_adj -> smem scores
        const int qr_lo = q0 + r_lo;
        #pragma unroll
        for (int nt = 0; nt < 2; nt++) {
            int kc = kt * TK + wn * 16 + nt * 8 + 2 * tg;
            const float2 rl = *(const float2*)(g_resc + ((size_t)b * NS + qr_lo) * NS + kc);
            const float2 al = *(const float2*)(g_madj + ((size_t)b * NS + qr_lo) * NS + kc);
            const float2 rh = *(const float2*)(g_resc + ((size_t)b * NS + qr_lo + 8) * NS + kc);
            const float2 ah = *(const float2*)(g_madj + ((size_t)b * NS + qr_lo + 8) * NS + kc);
            float2 s0, s1;
            s0.x = fmaxf(c4[nt][0], 0.0f) * rl.x + al.x;
            s0.y = fmaxf(c4[nt][1], 0.0f) * rl.y + al.y;
            s1.x = fmaxf(c4[nt][2], 0.0f) * rh.x + ah.x;
            s1.y = fmaxf(c4[nt][3], 0.0f) * rh.y + ah.y;
            *(float2*)(sc + r_lo * SCS + kc) = s0;
            *(float2*)(sc + (r_lo + 8) * SCS + kc) = s1;
        }
        __syncthreads();

        if (kt + 2 < NS / TK) {
            float* dst = kbuf + (kt & 1) * TK * VSS;
            for (int i = tid; i < TK * 16; i += NT) {
                int r = i >> 4, c = (i & 15) << 2;
                cp_async16(dst + r * KSS + c,
                           kg + (size_t)((kt + 2) * TK + r) * ND + c);
            }
            CP_COMMIT();
        }
    }

    // ---- prefetch v tiles 0,1 (overlaps with softmax) ----
    for (int t = 0; t < 2; t++) {
        float* dst = kbuf + t * TK * VSS;
        for (int i = tid; i < TK * 16; i += NT) {
            int r = i >> 4, c = (i & 15) << 2;
            cp_async16(dst + r * VSS + c, vg + (size_t)(t * TK + r) * ND + c);
        }
        CP_COMMIT();
    }

    // ================= Phase B: softmax (warp per 2 rows) =================
    {
        #pragma unroll
        for (int i = 0; i < 2; i++) {
            int row = wid * 2 + i;
            float* sr = sc + row * SCS;
            float m = -1.0e30f;
            for (int c = lane; c < NS; c += 32) m = fmaxf(m, sr[c]);
            #pragma unroll
            for (int o = 16; o > 0; o >>= 1)
                m = fmaxf(m, __shfl_xor_sync(0xffffffffu, m, o));
            float ssum = 0.0f;
            for (int c = lane; c < NS; c += 32) {
                float p = __expf(sr[c] - m);
                sr[c] = p;
                ssum += p;
            }
            #pragma unroll
            for (int o = 16; o > 0; o >>= 1)
                ssum += __shfl_xor_sync(0xffffffffu, ssum, o);
            if (lane == 0) rinv[row] = 1.0f / ssum;
        }
    }
    __syncthreads();

    // ---- write normalized attn ----
    {
        float* ag = attn_out + (bh * NS + q0) * NS;
        for (int i = tid; i < TQ * (NS / 4); i += NT) {
            int row = i >> 8, c = (i & 255) << 2;
            float rv = rinv[row];
            float4 p = *(const float4*)(sc + row * SCS + c);
            p.x *= rv; p.y *= rv; p.z *= rv; p.w *= rv;
            *(float4*)(ag + (size_t)row * NS + c) = p;
        }
    }

    // ================= Phase C: out = P @ V (tf32, 2 acc chains) ==========
    const int n0 = wn * 8;
    float ca[4], cb[4];
    #pragma unroll
    for (int j = 0; j < 4; j++) { ca[j] = 0.0f; cb[j] = 0.0f; }

    for (int vt = 0; vt < NS / TK; vt++) {
        if (vt < 7) { CP_WAIT(1); } else { CP_WAIT(0); }
        __syncthreads();

        const float* vb = kbuf + (vt & 1) * TK * VSS;

        #pragma unroll
        for (int ks = 0; ks < 16; ks++) {
            int kcol = vt * TK + ks * 8;
            uint32_t a0 = f2tf(sc[r_lo * SCS + kcol + tg]);
            uint32_t a1 = f2tf(sc[(r_lo + 8) * SCS + kcol + tg]);
            uint32_t a2 = f2tf(sc[r_lo * SCS + kcol + tg + 4]);
            uint32_t a3 = f2tf(sc[(r_lo + 8) * SCS + kcol + tg + 4]);
            uint32_t b0 = f2tf(vb[(ks * 8 + tg) * VSS + n0 + g]);
            uint32_t b1 = f2tf(vb[(ks * 8 + tg + 4) * VSS + n0 + g]);
            if (ks & 1)
                mma_tf32(cb[0], cb[1], cb[2], cb[3], a0, a1, a2, a3, b0, b1);
            else
                mma_tf32(ca[0], ca[1], ca[2], ca[3], a0, a1, a2, a3, b0, b1);
        }
        __syncthreads();

        if (vt + 2 < NS / TK) {
            float* dst = kbuf + (vt & 1) * TK * VSS;
            for (int i = tid; i < TK * 16; i += NT) {
                int r = i >> 4, c = (i & 15) << 2;
                cp_async16(dst + r * VSS + c,
                           vg + (size_t)((vt + 2) * TK + r) * ND + c);
            }
            CP_COMMIT();
        }
    }

    // ---- epilogue: normalize + write out ----
    {
        float rv_lo = rinv[r_lo];
        float rv_hi = rinv[r_lo + 8];
        int col = n0 + 2 * tg;
        float2 o0, o1;
        o0.x = (ca[0] + cb[0]) * rv_lo; o0.y = (ca[1] + cb[1]) * rv_lo;
        o1.x = (ca[2] + cb[2]) * rv_hi; o1.y = (ca[3] + cb[3]) * rv_hi;
        *(float2*)(out + (bh * NS + (size_t)(q0 + r_lo)) * ND + col) = o0;
        *(float2*)(out + (bh * NS + (size_t)(q0 + r_lo + 8)) * ND + col) = o1;
    }
}

extern "C" void kernel_launch(void* const* d_in, const int* in_sizes, int n_in,
                              void* d_out, int out_size) {
    const float* q    = (const float*)d_in[0];
    const float* k    = (const float*)d_in[1];
    const float* v    = (const float*)d_in[2];
    const int*   mask = (const int*)  d_in[3];
    const float* adj  = (const float*)d_in[4];
    const float* dist = (const float*)d_in[5];

    float* out  = (float*)d_out;                      // [B,H,S,D]
    float* attn = out + (size_t)NB * NH * NS * ND;    // [B,H,S,S]

    prep_kernel<<<(NB * NS * NS) / 256, 256>>>(dist, adj, mask);

    const size_t smem_bytes =
        (size_t)(2 * TQ * QSS + 2 * TK * VSS + TQ * SCS + TQ) * sizeof(float);
    cudaFuncSetAttribute(attn_kernel,
                         cudaFuncAttributeMaxDynamicSharedMemorySize,
                         (int)smem_bytes);

    dim3 grid(NS / TQ, NH, NB);
    attn_kernel<<<grid, NT, smem_bytes>>>(q, k, v, out, attn);
}

// round 5
// speedup vs baseline: 1.8098x; 1.0329x over previous
#include <cuda_runtime.h>
#include <cuda_bf16.h>
#include <math.h>
#include <stdint.h>

#define NB 4
#define NH 16
#define NS 1024
#define ND 64
#define TQ 32
#define TK 128
#define NT 512

#define QHS 68      // q packed tile stride (words), mod 32 == 4
#define KHS 68      // k packed tile stride (words), mod 32 == 4
#define VSS 72      // v tile stride, mod 32 == 8
#define SCS 1028    // scores stride, mod 32 == 4

// Precomputed, head-independent tables.
__device__ float    g_resc[NB * NS * NS];        // (1+e)/(1+exp(1-dist))
__device__ float    g_madj[NB * NS * NS];        // mask ? adj : -1e9
__device__ uint32_t g_khl[NB * NH * NS * ND];    // k packed bf16 hi|lo
__device__ float    g_vtf[NB * NH * NS * ND];    // tf32(v) bits

__global__ void prep_kernel(const float* __restrict__ dist,
                            const float* __restrict__ adj,
                            const int*   __restrict__ mask) {
    int i = blockIdx.x * blockDim.x + threadIdx.x;
    int b = i >> 20;
    int j = i & (NS - 1);
    float d = dist[i];
    g_resc[i] = 3.7182817f / (1.0f + __expf(1.0f - d));
    g_madj[i] = (mask[b * NS + j] == 0) ? -1.0e9f : adj[i];
}

__device__ __forceinline__ uint32_t f2tf(float f) {
    uint32_t r;
    asm("cvt.rna.tf32.f32 %0, %1;" : "=r"(r) : "f"(f));
    return r;
}
__device__ __forceinline__ uint32_t pack_bf16x2_split(float f) {
    __nv_bfloat16 h = __float2bfloat16(f);
    float resid = f - __bfloat162float(h);
    __nv_bfloat16 l = __float2bfloat16(resid);
    uint16_t hu = __bfloat16_as_ushort(h);
    uint16_t lu = __bfloat16_as_ushort(l);
    return (uint32_t)hu | ((uint32_t)lu << 16);
}

__global__ void prep_kv_kernel(const float* __restrict__ k,
                               const float* __restrict__ v) {
    int i = blockIdx.x * blockDim.x + threadIdx.x;
    g_khl[i] = pack_bf16x2_split(k[i]);
    g_vtf[i] = __uint_as_float(f2tf(v[i]));
}

__device__ __forceinline__ void mma_bf16(float& c0, float& c1, float& c2, float& c3,
                                         uint32_t a0, uint32_t a1, uint32_t a2, uint32_t a3,
                                         uint32_t b0, uint32_t b1) {
    asm volatile("mma.sync.aligned.m16n8k16.row.col.f32.bf16.bf16.f32 "
                 "{%0,%1,%2,%3}, {%4,%5,%6,%7}, {%8,%9}, {%0,%1,%2,%3};"
                 : "+f"(c0), "+f"(c1), "+f"(c2), "+f"(c3)
                 : "r"(a0), "r"(a1), "r"(a2), "r"(a3), "r"(b0), "r"(b1));
}
__device__ __forceinline__ void mma_tf32(float& c0, float& c1, float& c2, float& c3,
                                         uint32_t a0, uint32_t a1, uint32_t a2, uint32_t a3,
                                         uint32_t b0, uint32_t b1) {
    asm volatile("mma.sync.aligned.m16n8k8.row.col.f32.tf32.tf32.f32 "
                 "{%0,%1,%2,%3}, {%4,%5,%6,%7}, {%8,%9}, {%0,%1,%2,%3};"
                 : "+f"(c0), "+f"(c1), "+f"(c2), "+f"(c3)
                 : "r"(a0), "r"(a1), "r"(a2), "r"(a3), "r"(b0), "r"(b1));
}

__device__ __forceinline__ void cp_async16(void* smem_dst, const void* gsrc) {
    uint32_t sa = (uint32_t)__cvta_generic_to_shared(smem_dst);
    asm volatile("cp.async.cg.shared.global [%0], [%1], 16;" :: "r"(sa), "l"(gsrc));
}
#define CP_COMMIT()  asm volatile("cp.async.commit_group;")
#define CP_WAIT(n)   asm volatile("cp.async.wait_group %0;" :: "n"(n))

__global__ __launch_bounds__(NT, 1)
void attn_kernel(const float* __restrict__ q,
                 float*       __restrict__ out,
                 float*       __restrict__ attn_out) {
    extern __shared__ float smem[];
    uint32_t* qhl  = (uint32_t*)smem;                 // TQ * QHS words
    float*    kbuf = smem + TQ * QHS;                 // 2 * TK * VSS (k: KHS words, v: VSS)
    float*    sc   = kbuf + 2 * TK * VSS;             // TQ * SCS
    float*    rinv = sc + TQ * SCS;                   // TQ

    const int tid  = threadIdx.x;
    const int wid  = tid >> 5;
    const int lane = tid & 31;
    const int g    = lane >> 2;
    const int tg   = lane & 3;
    const int wm   = wid >> 3;    // 0..1
    const int wn   = wid & 7;     // 0..7

    const int q0 = blockIdx.x * TQ;
    const int h  = blockIdx.y;
    const int b  = blockIdx.z;
    const size_t bh = (size_t)b * NH + h;

    const float*    qg  = q + (bh * NS + q0) * ND;
    const uint32_t* khg = g_khl + bh * NS * ND;
    const float*    vg  = g_vtf + bh * NS * ND;

    // ---- prefetch k packed tiles 0,1 ----
    for (int t = 0; t < 2; t++) {
        uint32_t* dst = (uint32_t*)(kbuf + t * TK * VSS);
        for (int i = tid; i < TK * 16; i += NT) {
            int r = i >> 4, c = (i & 15) << 2;
            cp_async16(dst + r * KHS + c, khg + (size_t)(t * TK + r) * ND + c);
        }
        CP_COMMIT();
    }

    // ---- load q tile, prescale by 1/8, split+pack bf16x2 ----
    {
        int r = tid >> 4, c = (tid & 15) << 2;   // exactly TQ*16 chunks
        float4 t = *(const float4*)(qg + (size_t)r * ND + c);
        uint32_t* dq = qhl + r * QHS + c;
        dq[0] = pack_bf16x2_split(t.x * 0.125f);
        dq[1] = pack_bf16x2_split(t.y * 0.125f);
        dq[2] = pack_bf16x2_split(t.z * 0.125f);
        dq[3] = pack_bf16x2_split(t.w * 0.125f);
    }

    const int m0   = wm * 16;
    const int r_lo = m0 + g;

    // ========== Phase A: scores = QK^T (packed bf16x2, 2 mma/k8) ==========
    for (int kt = 0; kt < NS / TK; kt++) {
        if (kt < 7) { CP_WAIT(1); } else { CP_WAIT(0); }
        __syncthreads();

        const uint32_t* kw = (const uint32_t*)(kbuf + (kt & 1) * TK * VSS);

        float c4[2][4];
        #pragma unroll
        for (int nt = 0; nt < 2; nt++)
            #pragma unroll
            for (int j = 0; j < 4; j++) c4[nt][j] = 0.0f;

        #pragma unroll
        for (int ks = 0; ks < 8; ks++) {
            int col = ks * 8 + tg;
            uint32_t ap0 = qhl[r_lo * QHS + col];
            uint32_t ap1 = qhl[(r_lo + 8) * QHS + col];
            uint32_t ap2 = qhl[r_lo * QHS + col + 4];
            uint32_t ap3 = qhl[(r_lo + 8) * QHS + col + 4];
            uint32_t ahh0 = __byte_perm(ap0, ap0, 0x1010);
            uint32_t ahh1 = __byte_perm(ap1, ap1, 0x1010);
            uint32_t ahh2 = __byte_perm(ap2, ap2, 0x1010);
            uint32_t ahh3 = __byte_perm(ap3, ap3, 0x1010);
            uint32_t all0 = __byte_perm(ap0, ap0, 0x3232);
            uint32_t all1 = __byte_perm(ap1, ap1, 0x3232);
            uint32_t all2 = __byte_perm(ap2, ap2, 0x3232);
            uint32_t all3 = __byte_perm(ap3, ap3, 0x3232);
            #pragma unroll
            for (int nt = 0; nt < 2; nt++) {
                int nloc = wn * 16 + nt * 8;
                uint32_t bp0 = kw[(nloc + g) * KHS + col];
                uint32_t bp1 = kw[(nloc + g) * KHS + col + 4];
                mma_bf16(c4[nt][0], c4[nt][1], c4[nt][2], c4[nt][3],
                         ahh0, ahh1, ahh2, ahh3, bp0, bp1);
                mma_bf16(c4[nt][0], c4[nt][1], c4[nt][2], c4[nt][3],
                         all0, all1, all2, all3, bp0, bp1);
            }
        }

        // epilogue: relu * rescale + masked_adj -> smem scores
        const int qr_lo = q0 + r_lo;
        #pragma unroll
        for (int nt = 0; nt < 2; nt++) {
            int kc = kt * TK + wn * 16 + nt * 8 + 2 * tg;
            const float2 rl = *(const float2*)(g_resc + ((size_t)b * NS + qr_lo) * NS + kc);
            const float2 al = *(const float2*)(g_madj + ((size_t)b * NS + qr_lo) * NS + kc);
            const float2 rh = *(const float2*)(g_resc + ((size_t)b * NS + qr_lo + 8) * NS + kc);
            const float2 ah = *(const float2*)(g_madj + ((size_t)b * NS + qr_lo + 8) * NS + kc);
            float2 s0, s1;
            s0.x = fmaxf(c4[nt][0], 0.0f) * rl.x + al.x;
            s0.y = fmaxf(c4[nt][1], 0.0f) * rl.y + al.y;
            s1.x = fmaxf(c4[nt][2], 0.0f) * rh.x + ah.x;
            s1.y = fmaxf(c4[nt][3], 0.0f) * rh.y + ah.y;
            *(float2*)(sc + r_lo * SCS + kc) = s0;
            *(float2*)(sc + (r_lo + 8) * SCS + kc) = s1;
        }
        __syncthreads();

        if (kt + 2 < NS / TK) {
            uint32_t* dst = (uint32_t*)(kbuf + (kt & 1) * TK * VSS);
            for (int i = tid; i < TK * 16; i += NT) {
                int r = i >> 4, c = (i & 15) << 2;
                cp_async16(dst + r * KHS + c,
                           khg + (size_t)((kt + 2) * TK + r) * ND + c);
            }
            CP_COMMIT();
        }
    }

    // ---- prefetch v (tf32 bits) tiles 0,1 (overlaps softmax) ----
    for (int t = 0; t < 2; t++) {
        float* dst = kbuf + t * TK * VSS;
        for (int i = tid; i < TK * 16; i += NT) {
            int r = i >> 4, c = (i & 15) << 2;
            cp_async16(dst + r * VSS + c, vg + (size_t)(t * TK + r) * ND + c);
        }
        CP_COMMIT();
    }

    // ================= Phase B: softmax (warp per 2 rows) =================
    {
        #pragma unroll
        for (int i = 0; i < 2; i++) {
            int row = wid * 2 + i;
            float* sr = sc + row * SCS;
            float m = -1.0e30f;
            for (int c = lane; c < NS; c += 32) m = fmaxf(m, sr[c]);
            #pragma unroll
            for (int o = 16; o > 0; o >>= 1)
                m = fmaxf(m, __shfl_xor_sync(0xffffffffu, m, o));
            float ssum = 0.0f;
            for (int c = lane; c < NS; c += 32) {
                float p = __expf(sr[c] - m);
                sr[c] = p;
                ssum += p;
            }
            #pragma unroll
            for (int o = 16; o > 0; o >>= 1)
                ssum += __shfl_xor_sync(0xffffffffu, ssum, o);
            if (lane == 0) rinv[row] = 1.0f / ssum;
        }
    }
    __syncthreads();

    // ---- write normalized attn; convert sc -> tf32 bits in place ----
    {
        float* ag = attn_out + (bh * NS + q0) * NS;
        for (int i = tid; i < TQ * (NS / 4); i += NT) {
            int row = i >> 8, c = (i & 255) << 2;
            float rv = rinv[row];
            float4 p = *(const float4*)(sc + row * SCS + c);
            float4 w;
            w.x = p.x * rv; w.y = p.y * rv; w.z = p.z * rv; w.w = p.w * rv;
            *(float4*)(ag + (size_t)row * NS + c) = w;
            float4 t;
            t.x = __uint_as_float(f2tf(p.x));
            t.y = __uint_as_float(f2tf(p.y));
            t.z = __uint_as_float(f2tf(p.z));
            t.w = __uint_as_float(f2tf(p.w));
            *(float4*)(sc + row * SCS + c) = t;
        }
    }

    // ========== Phase C: out = P @ V (tf32, zero in-loop cvt) ==========
    const int n0 = wn * 8;
    float ca[4], cb[4];
    #pragma unroll
    for (int j = 0; j < 4; j++) { ca[j] = 0.0f; cb[j] = 0.0f; }

    for (int vt = 0; vt < NS / TK; vt++) {
        if (vt < 7) { CP_WAIT(1); } else { CP_WAIT(0); }
        __syncthreads();

        const float* vb = kbuf + (vt & 1) * TK * VSS;

        #pragma unroll
        for (int ks = 0; ks < 16; ks++) {
            int kcol = vt * TK + ks * 8;
            uint32_t a0 = __float_as_uint(sc[r_lo * SCS + kcol + tg]);
            uint32_t a1 = __float_as_uint(sc[(r_lo + 8) * SCS + kcol + tg]);
            uint32_t a2 = __float_as_uint(sc[r_lo * SCS + kcol + tg + 4]);
            uint32_t a3 = __float_as_uint(sc[(r_lo + 8) * SCS + kcol + tg + 4]);
            uint32_t b0 = __float_as_uint(vb[(ks * 8 + tg) * VSS + n0 + g]);
            uint32_t b1 = __float_as_uint(vb[(ks * 8 + tg + 4) * VSS + n0 + g]);
            if (ks & 1)
                mma_tf32(cb[0], cb[1], cb[2], cb[3], a0, a1, a2, a3, b0, b1);
            else
                mma_tf32(ca[0], ca[1], ca[2], ca[3], a0, a1, a2, a3, b0, b1);
        }
        __syncthreads();

        if (vt + 2 < NS / TK) {
            float* dst = kbuf + (vt & 1) * TK * VSS;
            for (int i = tid; i < TK * 16; i += NT) {
                int r = i >> 4, c = (i & 15) << 2;
                cp_async16(dst + r * VSS + c,
                           vg + (size_t)((vt + 2) * TK + r) * ND + c);
            }
            CP_COMMIT();
        }
    }

    // ---- epilogue: normalize + write out ----
    {
        float rv_lo = rinv[r_lo];
        float rv_hi = rinv[r_lo + 8];
        int col = n0 + 2 * tg;
        float2 o0, o1;
        o0.x = (ca[0] + cb[0]) * rv_lo; o0.y = (ca[1] + cb[1]) * rv_lo;
        o1.x = (ca[2] + cb[2]) * rv_hi; o1.y = (ca[3] + cb[3]) * rv_hi;
        *(float2*)(out + (bh * NS + (size_t)(q0 + r_lo)) * ND + col) = o0;
        *(float2*)(out + (bh * NS + (size_t)(q0 + r_lo + 8)) * ND + col) = o1;
    }
}

extern "C" void kernel_launch(void* const* d_in, const int* in_sizes, int n_in,
                              void* d_out, int out_size) {
    const float* q    = (const float*)d_in[0];
    const float* k    = (const float*)d_in[1];
    const float* v    = (const float*)d_in[2];
    const int*   mask = (const int*)  d_in[3];
    const float* adj  = (const float*)d_in[4];
    const float* dist = (const float*)d_in[5];

    float* out  = (float*)d_out;                      // [B,H,S,D]
    float* attn = out + (size_t)NB * NH * NS * ND;    // [B,H,S,S]

    prep_kernel<<<(NB * NS * NS) / 256, 256>>>(dist, adj, mask);
    prep_kv_kernel<<<(NB * NH * NS * ND) / 256, 256>>>(k, v);

    const size_t smem_bytes =
        (size_t)(TQ * QHS + 2 * TK * VSS + TQ * SCS + TQ) * sizeof(float);
    cudaFuncSetAttribute(attn_kernel,
                         cudaFuncAttributeMaxDynamicSharedMemorySize,
                         (int)smem_bytes);

    dim3 grid(NS / TQ, NH, NB);
    attn_kernel<<<grid, NT, smem_bytes>>>(q, out, attn);
}

// round 6
// speedup vs baseline: 2.2100x; 1.2211x over previous
#include <cuda_runtime.h>
#include <cuda_bf16.h>
#include <math.h>
#include <stdint.h>

#define NB 4
#define NH 16
#define NS 1024
#define ND 64
#define TQ 32
#define TK 128
#define NT 512

#define QHS 68      // q packed tile stride (words), mod 32 == 4
#define KHS 68      // k packed tile stride (words), mod 32 == 4
#define VSS 72      // v tile stride, mod 32 == 8
#define SCS 1028    // scores stride, mod 32 == 4
#define PRS 68      // reduction scratch stride

// Precomputed, head-independent tables.
__device__ float    g_resc[NB * NS * NS];        // (1+e)/(1+exp(1-dist))
__device__ float    g_madj[NB * NS * NS];        // mask ? adj : -1e9
__device__ uint32_t g_qhl[NB * NH * NS * ND];    // q/8 packed bf16 hi|lo
__device__ uint32_t g_khl[NB * NH * NS * ND];    // k packed bf16 hi|lo
__device__ float    g_vtf[NB * NH * NS * ND];    // tf32(v) bits

__global__ void prep_kernel(const float* __restrict__ dist,
                            const float* __restrict__ adj,
                            const int*   __restrict__ mask) {
    int i = blockIdx.x * blockDim.x + threadIdx.x;
    int b = i >> 20;
    int j = i & (NS - 1);
    float d = dist[i];
    g_resc[i] = 3.7182817f / (1.0f + __expf(1.0f - d));
    g_madj[i] = (mask[b * NS + j] == 0) ? -1.0e9f : adj[i];
}

__device__ __forceinline__ uint32_t f2tf(float f) {
    uint32_t r;
    asm("cvt.rna.tf32.f32 %0, %1;" : "=r"(r) : "f"(f));
    return r;
}
__device__ __forceinline__ uint32_t pack_bf16x2_split(float f) {
    __nv_bfloat16 h = __float2bfloat16(f);
    float resid = f - __bfloat162float(h);
    __nv_bfloat16 l = __float2bfloat16(resid);
    return (uint32_t)__bfloat16_as_ushort(h) |
           ((uint32_t)__bfloat16_as_ushort(l) << 16);
}

__global__ void prep_qkv_kernel(const float* __restrict__ q,
                                const float* __restrict__ k,
                                const float* __restrict__ v) {
    int i = blockIdx.x * blockDim.x + threadIdx.x;
    g_qhl[i] = pack_bf16x2_split(q[i] * 0.125f);
    g_khl[i] = pack_bf16x2_split(k[i]);
    g_vtf[i] = __uint_as_float(f2tf(v[i]));
}

__device__ __forceinline__ void mma_bf16(float* c,
                                         uint32_t a0, uint32_t a1, uint32_t a2, uint32_t a3,
                                         uint32_t b0, uint32_t b1) {
    asm volatile("mma.sync.aligned.m16n8k16.row.col.f32.bf16.bf16.f32 "
                 "{%0,%1,%2,%3}, {%4,%5,%6,%7}, {%8,%9}, {%0,%1,%2,%3};"
                 : "+f"(c[0]), "+f"(c[1]), "+f"(c[2]), "+f"(c[3])
                 : "r"(a0), "r"(a1), "r"(a2), "r"(a3), "r"(b0), "r"(b1));
}
__device__ __forceinline__ void mma_tf32(float* c,
                                         uint32_t a0, uint32_t a1, uint32_t a2, uint32_t a3,
                                         uint32_t b0, uint32_t b1) {
    asm volatile("mma.sync.aligned.m16n8k8.row.col.f32.tf32.tf32.f32 "
                 "{%0,%1,%2,%3}, {%4,%5,%6,%7}, {%8,%9}, {%0,%1,%2,%3};"
                 : "+f"(c[0]), "+f"(c[1]), "+f"(c[2]), "+f"(c[3])
                 : "r"(a0), "r"(a1), "r"(a2), "r"(a3), "r"(b0), "r"(b1));
}

__device__ __forceinline__ void cp_async16(void* smem_dst, const void* gsrc) {
    uint32_t sa = (uint32_t)__cvta_generic_to_shared(smem_dst);
    asm volatile("cp.async.cg.shared.global [%0], [%1], 16;" :: "r"(sa), "l"(gsrc));
}
#define CP_COMMIT()  asm volatile("cp.async.commit_group;")
#define CP_WAIT(n)   asm volatile("cp.async.wait_group %0;" :: "n"(n))

__global__ __launch_bounds__(NT, 1)
void attn_kernel(float* __restrict__ out,
                 float* __restrict__ attn_out) {
    extern __shared__ float smem[];
    uint32_t* qhl_s = (uint32_t*)smem;                // TQ * QHS words (2176)
    float*    kbuf  = smem + TQ * QHS;                // 2 * TK * VSS   (18432)
    float*    sc    = kbuf + 2 * TK * VSS;            // TQ * SCS       (32896) ; reused as reduce scratch
    float*    rs_sm = sc + TQ * SCS;                  // 32
    float*    rinv  = rs_sm + 32;                     // 32

    const int tid  = threadIdx.x;
    const int wid  = tid >> 5;
    const int lane = tid & 31;
    const int g    = lane >> 2;
    const int tg   = lane & 3;
    const int wm   = wid >> 3;    // 0..1  (m16 group)
    const int wn   = wid & 7;     // 0..7  (Phase A: n16 group; Phase C: k16 slice)

    const int q0 = blockIdx.x * TQ;
    const int h  = blockIdx.y;
    const int b  = blockIdx.z;
    const size_t bh = (size_t)b * NH + h;

    const uint32_t* qg  = g_qhl + (bh * NS + q0) * ND;
    const uint32_t* khg = g_khl + bh * NS * ND;
    const float*    vg  = g_vtf + bh * NS * ND;

    if (tid < 32) rs_sm[tid] = 0.0f;

    // ---- cp.async q (group 0) ----
    {
        int r = tid >> 4, c = (tid & 15) << 2;
        cp_async16(qhl_s + r * QHS + c, qg + (size_t)r * ND + c);
    }
    CP_COMMIT();
    // ---- cp.async k tiles 0,1 (groups 1,2) ----
    for (int t = 0; t < 2; t++) {
        uint32_t* dst = (uint32_t*)(kbuf + t * TK * VSS);
        for (int i = tid; i < TK * 16; i += NT) {
            int r = i >> 4, c = (i & 15) << 2;
            cp_async16(dst + r * KHS + c, khg + (size_t)(t * TK + r) * ND + c);
        }
        CP_COMMIT();
    }
    CP_WAIT(2);
    __syncthreads();

    // ---- A fragments -> registers, pre-expanded hh/ll ----
    uint32_t ahh[8][4], all[8][4];
    const int r_lo = wm * 16 + g;
    #pragma unroll
    for (int ks = 0; ks < 8; ks++) {
        int col = ks * 8 + tg;
        uint32_t p0 = qhl_s[r_lo * QHS + col];
        uint32_t p1 = qhl_s[(r_lo + 8) * QHS + col];
        uint32_t p2 = qhl_s[r_lo * QHS + col + 4];
        uint32_t p3 = qhl_s[(r_lo + 8) * QHS + col + 4];
        ahh[ks][0] = __byte_perm(p0, p0, 0x1010);
        ahh[ks][1] = __byte_perm(p1, p1, 0x1010);
        ahh[ks][2] = __byte_perm(p2, p2, 0x1010);
        ahh[ks][3] = __byte_perm(p3, p3, 0x1010);
        all[ks][0] = __byte_perm(p0, p0, 0x3232);
        all[ks][1] = __byte_perm(p1, p1, 0x3232);
        all[ks][2] = __byte_perm(p2, p2, 0x3232);
        all[ks][3] = __byte_perm(p3, p3, 0x3232);
    }

    float rs0 = 0.0f, rs1 = 0.0f;

    // ========== Phase A: e = exp(relu(QK^T)*resc + madj) ==========
    for (int kt = 0; kt < NS / TK; kt++) {
        if (kt < 7) { CP_WAIT(1); } else { CP_WAIT(0); }
        __syncthreads();

        const uint32_t* kw = (const uint32_t*)(kbuf + (kt & 1) * TK * VSS);

        float c4[2][4];
        #pragma unroll
        for (int nt = 0; nt < 2; nt++)
            #pragma unroll
            for (int j = 0; j < 4; j++) c4[nt][j] = 0.0f;

        #pragma unroll
        for (int ks = 0; ks < 8; ks++) {
            int col = ks * 8 + tg;
            #pragma unroll
            for (int nt = 0; nt < 2; nt++) {
                int nloc = wn * 16 + nt * 8;
                uint32_t bp0 = kw[(nloc + g) * KHS + col];
                uint32_t bp1 = kw[(nloc + g) * KHS + col + 4];
                mma_bf16(c4[nt], ahh[ks][0], ahh[ks][1], ahh[ks][2], ahh[ks][3], bp0, bp1);
                mma_bf16(c4[nt], all[ks][0], all[ks][1], all[ks][2], all[ks][3], bp0, bp1);
            }
        }

        // fused epilogue: exp(relu*resc + madj), accumulate row sums
        const int qr = q0 + r_lo;
        #pragma unroll
        for (int nt = 0; nt < 2; nt++) {
            int kc = kt * TK + wn * 16 + nt * 8 + 2 * tg;
            const float2 rl = *(const float2*)(g_resc + ((size_t)b * NS + qr) * NS + kc);
            const float2 al = *(const float2*)(g_madj + ((size_t)b * NS + qr) * NS + kc);
            const float2 rh = *(const float2*)(g_resc + ((size_t)b * NS + qr + 8) * NS + kc);
            const float2 ah = *(const float2*)(g_madj + ((size_t)b * NS + qr + 8) * NS + kc);
            float e00 = __expf(fmaxf(c4[nt][0], 0.0f) * rl.x + al.x);
            float e01 = __expf(fmaxf(c4[nt][1], 0.0f) * rl.y + al.y);
            float e10 = __expf(fmaxf(c4[nt][2], 0.0f) * rh.x + ah.x);
            float e11 = __expf(fmaxf(c4[nt][3], 0.0f) * rh.y + ah.y);
            rs0 += e00 + e01;
            rs1 += e10 + e11;
            *(float2*)(sc + r_lo * SCS + kc) = make_float2(e00, e01);
            *(float2*)(sc + (r_lo + 8) * SCS + kc) = make_float2(e10, e11);
        }
        __syncthreads();

        if (kt + 2 < NS / TK) {
            uint32_t* dst = (uint32_t*)(kbuf + (kt & 1) * TK * VSS);
            for (int i = tid; i < TK * 16; i += NT) {
                int r = i >> 4, c = (i & 15) << 2;
                cp_async16(dst + r * KHS + c,
                           khg + (size_t)((kt + 2) * TK + r) * ND + c);
            }
            CP_COMMIT();
        }
    }

    // ---- prefetch v tiles 0,1 (overlaps row-sum + normalize) ----
    for (int t = 0; t < 2; t++) {
        float* dst = kbuf + t * TK * VSS;
        for (int i = tid; i < TK * 16; i += NT) {
            int r = i >> 4, c = (i & 15) << 2;
            cp_async16(dst + r * VSS + c, vg + (size_t)(t * TK + r) * ND + c);
        }
        CP_COMMIT();
    }

    // ---- row sums: quad reduce + smem atomic ----
    rs0 += __shfl_xor_sync(0xffffffffu, rs0, 1);
    rs0 += __shfl_xor_sync(0xffffffffu, rs0, 2);
    rs1 += __shfl_xor_sync(0xffffffffu, rs1, 1);
    rs1 += __shfl_xor_sync(0xffffffffu, rs1, 2);
    if (tg == 0) {
        atomicAdd(&rs_sm[r_lo], rs0);
        atomicAdd(&rs_sm[r_lo + 8], rs1);
    }
    __syncthreads();
    if (tid < 32) rinv[tid] = 1.0f / rs_sm[tid];
    __syncthreads();

    // ---- write normalized attn; convert sc -> tf32 bits in place ----
    {
        float* ag = attn_out + (bh * NS + q0) * NS;
        for (int i = tid; i < TQ * (NS / 4); i += NT) {
            int row = i >> 8, c = (i & 255) << 2;
            float rv = rinv[row];
            float4 p = *(const float4*)(sc + row * SCS + c);
            float4 w;
            w.x = p.x * rv; w.y = p.y * rv; w.z = p.z * rv; w.w = p.w * rv;
            *(float4*)(ag + (size_t)row * NS + c) = w;
            float4 t;
            t.x = __uint_as_float(f2tf(p.x));
            t.y = __uint_as_float(f2tf(p.y));
            t.z = __uint_as_float(f2tf(p.z));
            t.w = __uint_as_float(f2tf(p.w));
            *(float4*)(sc + row * SCS + c) = t;
        }
    }

    // ========== Phase C: out = E @ V (tf32, k-split across 8 warps) ==========
    float acc[8][4];
    #pragma unroll
    for (int nt = 0; nt < 8; nt++)
        #pragma unroll
        for (int j = 0; j < 4; j++) acc[nt][j] = 0.0f;

    for (int vt = 0; vt < NS / TK; vt++) {
        if (vt < 7) { CP_WAIT(1); } else { CP_WAIT(0); }
        __syncthreads();

        const float* vb = kbuf + (vt & 1) * TK * VSS;

        #pragma unroll
        for (int s = 0; s < 2; s++) {
            int kl = wn * 16 + s * 8;                 // warp's k-slice within tile
            int kcol = vt * TK + kl;
            uint32_t a0 = __float_as_uint(sc[r_lo * SCS + kcol + tg]);
            uint32_t a1 = __float_as_uint(sc[(r_lo + 8) * SCS + kcol + tg]);
            uint32_t a2 = __float_as_uint(sc[r_lo * SCS + kcol + tg + 4]);
            uint32_t a3 = __float_as_uint(sc[(r_lo + 8) * SCS + kcol + tg + 4]);
            #pragma unroll
            for (int nt = 0; nt < 8; nt++) {
                uint32_t b0 = __float_as_uint(vb[(kl + tg) * VSS + nt * 8 + g]);
                uint32_t b1 = __float_as_uint(vb[(kl + tg + 4) * VSS + nt * 8 + g]);
                mma_tf32(acc[nt], a0, a1, a2, a3, b0, b1);
            }
        }
        __syncthreads();

        if (vt + 2 < NS / TK) {
            float* dst = kbuf + (vt & 1) * TK * VSS;
            for (int i = tid; i < TK * 16; i += NT) {
                int r = i >> 4, c = (i & 15) << 2;
                cp_async16(dst + r * VSS + c,
                           vg + (size_t)((vt + 2) * TK + r) * ND + c);
            }
            CP_COMMIT();
        }
    }

    // ---- cross-warp k reduction via sc scratch ----
    {
        float* reg = sc + wid * 16 * PRS;
        #pragma unroll
        for (int nt = 0; nt < 8; nt++) {
            *(float2*)(reg + g * PRS + nt * 8 + 2 * tg) = make_float2(acc[nt][0], acc[nt][1]);
            *(float2*)(reg + (g + 8) * PRS + nt * 8 + 2 * tg) = make_float2(acc[nt][2], acc[nt][3]);
        }
    }
    __syncthreads();
    {
        int row = tid >> 4;            // 0..31
        int c4  = (tid & 15) << 2;     // 0..60
        int wmr = row >> 4, lrow = row & 15;
        float4 s = make_float4(0.f, 0.f, 0.f, 0.f);
        #pragma unroll
        for (int k = 0; k < 8; k++) {
            const float4 p = *(const float4*)(sc + ((wmr * 8 + k) * 16 + lrow) * PRS + c4);
            s.x += p.x; s.y += p.y; s.z += p.z; s.w += p.w;
        }
        float rv = rinv[row];
        s.x *= rv; s.y *= rv; s.z *= rv; s.w *= rv;
        *(float4*)(out + (bh * NS + (size_t)(q0 + row)) * ND + c4) = s;
    }
}

extern "C" void kernel_launch(void* const* d_in, const int* in_sizes, int n_in,
                              void* d_out, int out_size) {
    const float* q    = (const float*)d_in[0];
    const float* k    = (const float*)d_in[1];
    const float* v    = (const float*)d_in[2];
    const int*   mask = (const int*)  d_in[3];
    const float* adj  = (const float*)d_in[4];
    const float* dist = (const float*)d_in[5];

    float* out  = (float*)d_out;                      // [B,H,S,D]
    float* attn = out + (size_t)NB * NH * NS * ND;    // [B,H,S,S]

    prep_kernel<<<(NB * NS * NS) / 256, 256>>>(dist, adj, mask);
    prep_qkv_kernel<<<(NB * NH * NS * ND) / 256, 256>>>(q, k, v);

    const size_t smem_bytes =
        (size_t)(TQ * QHS + 2 * TK * VSS + TQ * SCS + 64) * sizeof(float);
    cudaFuncSetAttribute(attn_kernel,
                         cudaFuncAttributeMaxDynamicSharedMemorySize,
                         (int)smem_bytes);

    dim3 grid(NS / TQ, NH, NB);
    attn_kernel<<<grid, NT, smem_bytes>>>(out, attn);
}